// round 1
// baseline (speedup 1.0000x reference)
#include <cuda_runtime.h>
#include <math.h>

#define T_STEPS 100
#define MDIM 16
#define NDIM 16
#define H1D  2560      // W1 rows, GRU input dim
#define H2D  1024
#define HIDD 5120
#define NBLK 320
#define NTHR 256
#define NWARP (NBLK * (NTHR/32))   // 2560 warps

// ---------------- persistent device state ----------------
__device__ float g_l1[H1D];
__device__ float g_hbuf[2][HIDD];
__device__ float g_l2[H2D];
__device__ float g_KG[MDIM * NDIM];
__device__ float g_m1x[2][MDIM];
__device__ float g_m1y[2][NDIM];
__device__ float g_spp[2][MDIM];
__device__ unsigned g_count;
__device__ volatile unsigned g_gen;

__global__ void init_kernel(const float* __restrict__ h0) {
    int i = blockIdx.x * blockDim.x + threadIdx.x;
    if (i < HIDD) g_hbuf[0][i] = h0[i];
    if (i == 0) { g_count = 0; g_gen = 0; }
}

// ---------------- grid-wide spin barrier ----------------
__device__ __forceinline__ void gsync(unsigned target) {
    __syncthreads();
    if (threadIdx.x == 0) {
        __threadfence();
        if (atomicAdd(&g_count, 1u) == gridDim.x - 1) {
            atomicExch(&g_count, 0u);
            __threadfence();
            g_gen = target;
        } else {
            while (g_gen < target) { __nanosleep(64); }
        }
        __threadfence();
    }
    __syncthreads();
}

__device__ __forceinline__ float wredsum(float v) {
#pragma unroll
    for (int o = 16; o > 0; o >>= 1) v += __shfl_xor_sync(0xffffffffu, v, o);
    return v;
}

__device__ __forceinline__ float sigmoidf_(float x) {
    return 1.0f / (1.0f + __expf(-x));
}

__global__ void __launch_bounds__(NTHR, 3)
knet_kernel(const float* __restrict__ y,  const float* __restrict__ F,
            const float* __restrict__ Hm, const float* __restrict__ m1_0,
            const float* __restrict__ W1, const float* __restrict__ b1,
            const float* __restrict__ Wih, const float* __restrict__ bih,
            const float* __restrict__ Whh, const float* __restrict__ bhh,
            const float* __restrict__ W2, const float* __restrict__ b2,
            const float* __restrict__ W3, const float* __restrict__ b3,
            float* __restrict__ out)
{
    const int tid  = threadIdx.x;
    const int lane = tid & 31;
    const int wid  = blockIdx.x * (NTHR / 32) + (tid >> 5);  // 0..2559
    unsigned lg = 0;

    __shared__ float s_post[16], s_spold[16], s_m1x[16], s_spnew[16];
    __shared__ float s_d[16], s_e[16], s_kin[32], s_nrm[2];

    for (int t = 0; t < T_STEPS; ++t) {
        const int cur = t & 1, prev = cur ^ 1;

        // ================= Phase A: post update + state + kin + l1 ==========
        if (tid < 16) {
            float p, sp;
            if (t == 0) {
                p = m1_0[tid]; sp = m1_0[tid];
            } else {
                float acc = g_m1x[prev][tid];
#pragma unroll
                for (int k = 0; k < 16; ++k)
                    acc += g_KG[tid * 16 + k] * (y[k * T_STEPS + (t - 1)] - g_m1y[prev][k]);
                p  = acc;
                sp = g_spp[prev][tid];
                if (blockIdx.x == 0) out[tid * T_STEPS + (t - 1)] = p;
            }
            s_post[tid] = p; s_spold[tid] = sp;
        }
        __syncthreads();
        if (tid < 16) {
            float mx = 0.f, sn = 0.f;
#pragma unroll
            for (int k = 0; k < 16; ++k) {
                float f = F[tid * 16 + k];
                mx += f * s_post[k];
                sn += f * s_spold[k];
            }
            s_m1x[tid] = mx; s_spnew[tid] = sn;
        }
        __syncthreads();
        if (tid < 16) {
            float my = 0.f, ob = 0.f;
#pragma unroll
            for (int k = 0; k < 16; ++k) {
                float h = Hm[tid * 16 + k];
                my += h * s_m1x[k];
                ob += h * s_spnew[k];
            }
            s_d[tid] = s_post[tid] - s_spold[tid];
            s_e[tid] = y[tid * T_STEPS + t] - ob;
            if (blockIdx.x == 0) {
                g_m1x[cur][tid] = s_m1x[tid];
                g_m1y[cur][tid] = my;
                g_spp[cur][tid] = s_spnew[tid];
            }
        }
        __syncthreads();
        if (tid == 0) {
            float nd = 0.f, ne = 0.f;
#pragma unroll
            for (int k = 0; k < 16; ++k) { nd += s_d[k] * s_d[k]; ne += s_e[k] * s_e[k]; }
            s_nrm[0] = fmaxf(sqrtf(nd), 1e-12f);
            s_nrm[1] = fmaxf(sqrtf(ne), 1e-12f);
        }
        __syncthreads();
        if (tid < 32)
            s_kin[tid] = (tid < 16) ? s_d[tid] / s_nrm[0] : s_e[tid - 16] / s_nrm[1];
        __syncthreads();

        // l1 = relu(W1 @ kin + b1): one warp per row (2560 warps == 2560 rows)
        {
            float v = W1[wid * 32 + lane] * s_kin[lane];
            v = wredsum(v);
            if (lane == 0) g_l1[wid] = fmaxf(v + b1[wid], 0.0f);
        }
        ++lg; gsync(lg);

        // ================= Phase B: fused GRU GEMV (h_new) ==================
        {
            const float*  hold = g_hbuf[cur];     // t=0 -> slot 0 holds h0
            float*        hnew = g_hbuf[prev];
            const float4* l1v  = (const float4*)g_l1;
            const float4* hv   = (const float4*)hold;
#pragma unroll
            for (int e = 0; e < 2; ++e) {
                const int j = wid + e * 2560;     // hidden element index
                float ar = 0.f, az = 0.f, an = 0.f;
                float br = 0.f, bz = 0.f, bn = 0.f;
                const float4* wr = (const float4*)(Wih + (long)(0 * HIDD + j) * H1D);
                const float4* wz = (const float4*)(Wih + (long)(1 * HIDD + j) * H1D);
                const float4* wn = (const float4*)(Wih + (long)(2 * HIDD + j) * H1D);
#pragma unroll 4
                for (int k = lane; k < H1D / 4; k += 32) {
                    float4 x = l1v[k];
                    float4 a = wr[k]; ar += a.x * x.x + a.y * x.y + a.z * x.z + a.w * x.w;
                    float4 b = wz[k]; az += b.x * x.x + b.y * x.y + b.z * x.z + b.w * x.w;
                    float4 c = wn[k]; an += c.x * x.x + c.y * x.y + c.z * x.z + c.w * x.w;
                }
                const float4* vr = (const float4*)(Whh + (long)(0 * HIDD + j) * HIDD);
                const float4* vz = (const float4*)(Whh + (long)(1 * HIDD + j) * HIDD);
                const float4* vn = (const float4*)(Whh + (long)(2 * HIDD + j) * HIDD);
#pragma unroll 4
                for (int k = lane; k < HIDD / 4; k += 32) {
                    float4 x = hv[k];
                    float4 a = vr[k]; br += a.x * x.x + a.y * x.y + a.z * x.z + a.w * x.w;
                    float4 b = vz[k]; bz += b.x * x.x + b.y * x.y + b.z * x.z + b.w * x.w;
                    float4 c = vn[k]; bn += c.x * x.x + c.y * x.y + c.z * x.z + c.w * x.w;
                }
                ar = wredsum(ar); az = wredsum(az); an = wredsum(an);
                br = wredsum(br); bz = wredsum(bz); bn = wredsum(bn);
                if (lane == 0) {
                    float r  = sigmoidf_(ar + bih[j]            + br + bhh[j]);
                    float z  = sigmoidf_(az + bih[HIDD + j]     + bz + bhh[HIDD + j]);
                    float nn = tanhf   (an + bih[2 * HIDD + j] + r * (bn + bhh[2 * HIDD + j]));
                    hnew[j] = (1.0f - z) * nn + z * hold[j];
                }
            }
        }
        ++lg; gsync(lg);

        // ================= Phase C: l2 = relu(W2 @ h_new + b2) ==============
        if (wid < H2D) {
            const float4* hv = (const float4*)g_hbuf[prev];   // h_new
            const float4* w  = (const float4*)(W2 + (long)wid * HIDD);
            float acc = 0.f;
#pragma unroll 4
            for (int k = lane; k < HIDD / 4; k += 32) {
                float4 a = w[k]; float4 x = hv[k];
                acc += a.x * x.x + a.y * x.y + a.z * x.z + a.w * x.w;
            }
            acc = wredsum(acc);
            if (lane == 0) g_l2[wid] = fmaxf(acc + b2[wid], 0.0f);
        }
        ++lg; gsync(lg);

        // ================= Phase D: KG = W3 @ l2 + b3 =======================
        if (wid < MDIM * NDIM) {
            const float4* lv = (const float4*)g_l2;
            const float4* w  = (const float4*)(W3 + (long)wid * H2D);
            float acc = 0.f;
#pragma unroll
            for (int k = lane; k < H2D / 4; k += 32) {
                float4 a = w[k]; float4 x = lv[k];
                acc += a.x * x.x + a.y * x.y + a.z * x.z + a.w * x.w;
            }
            acc = wredsum(acc);
            if (lane == 0) g_KG[wid] = acc + b3[wid];
        }
        ++lg; gsync(lg);
    }

    // ---- final output column (post update of step T-1) ----
    if (blockIdx.x == 0 && tid < 16) {
        const int pl = (T_STEPS - 1) & 1;
        float acc = g_m1x[pl][tid];
#pragma unroll
        for (int k = 0; k < 16; ++k)
            acc += g_KG[tid * 16 + k] * (y[k * T_STEPS + (T_STEPS - 1)] - g_m1y[pl][k]);
        out[tid * T_STEPS + (T_STEPS - 1)] = acc;
    }
}

extern "C" void kernel_launch(void* const* d_in, const int* in_sizes, int n_in,
                              void* d_out, int out_size) {
    const float* y    = (const float*)d_in[0];
    const float* F    = (const float*)d_in[1];
    const float* Hm   = (const float*)d_in[2];
    const float* m1_0 = (const float*)d_in[3];
    const float* h0   = (const float*)d_in[4];
    const float* W1   = (const float*)d_in[5];
    const float* b1   = (const float*)d_in[6];
    const float* Wih  = (const float*)d_in[7];
    const float* bih  = (const float*)d_in[8];
    const float* Whh  = (const float*)d_in[9];
    const float* bhh  = (const float*)d_in[10];
    const float* W2   = (const float*)d_in[11];
    const float* b2   = (const float*)d_in[12];
    const float* W3   = (const float*)d_in[13];
    const float* b3   = (const float*)d_in[14];
    float* out = (float*)d_out;

    init_kernel<<<20, 256>>>(h0);
    knet_kernel<<<NBLK, NTHR>>>(y, F, Hm, m1_0, W1, b1, Wih, bih,
                                Whh, bhh, W2, b2, W3, b3, out);
}